// round 1
// baseline (speedup 1.0000x reference)
#include <cuda_runtime.h>

#define NN   25000
#define EE   400000
#define FIN  256
#define CC   32
#define AA   9
#define WN   288     // CC*AA
#define BB   8
#define HH   64
#define SSP  4
#define FOUT 256

// scratch (static device arrays are the allowed scratch mechanism)
__device__ float g_h[NN * CC];      // 3.2 MB
__device__ float g_agg[NN * WN];    // 28.8 MB

__device__ __forceinline__ float silu_f(float v) {
    return v / (1.0f + __expf(-v));
}

// ---------------------------------------------------------------------------
// zero the aggregation buffer
// ---------------------------------------------------------------------------
__global__ void k_zero() {
    int i = blockIdx.x * blockDim.x + threadIdx.x;
    int stride = gridDim.x * blockDim.x;
    float4* p = (float4*)g_agg;
    const int n4 = (NN * WN) / 4;   // 1,800,000
    float4 z = make_float4(0.f, 0.f, 0.f, 0.f);
    for (; i < n4; i += stride) p[i] = z;
}

// ---------------------------------------------------------------------------
// h = 0.25 * (x @ W1)    [NN, CC]
// block: 256 threads -> 8 nodes x 32 channels
// ---------------------------------------------------------------------------
__global__ void __launch_bounds__(256) k_h(const float* __restrict__ x,
                                           const float* __restrict__ W1) {
    __shared__ float sW1[FIN * CC];      // 32 KB
    __shared__ float sX[8][FIN];         // 8 KB
    int t = threadIdx.x;
    int n0 = blockIdx.x * 8;
    for (int i = t; i < FIN * CC; i += 256) sW1[i] = W1[i];
    for (int i = t; i < 8 * FIN; i += 256)
        sX[i >> 8][i & 255] = x[(n0 + (i >> 8)) * FIN + (i & 255)];
    __syncthreads();
    int ty = t >> 5, tx = t & 31;
    float acc = 0.f;
#pragma unroll 8
    for (int f = 0; f < FIN; f++) acc += sX[ty][f] * sW1[f * CC + tx];
    g_h[(n0 + ty) * CC + tx] = 0.25f * acc;
}

// ---------------------------------------------------------------------------
// sc_out GEMM: out[n,o] = sum_k xa[n,k] * WscFlat[k,o], k = f*4+s, K=1024
// tile 64 x 128, block 256 threads, micro 4x8
// ---------------------------------------------------------------------------
__global__ void __launch_bounds__(256) k_sc(const float* __restrict__ x,
                                            const float* __restrict__ attrs,
                                            const float* __restrict__ Wsc,
                                            float* __restrict__ out) {
    __shared__ float sA[32][64];     // 8 KB
    __shared__ float sB[32][128];    // 16 KB
    int t = threadIdx.x;
    int n0 = blockIdx.x * 64;
    int o0 = blockIdx.y * 128;
    int tr = t >> 4;   // 0..15 -> node groups of 4
    int tc = t & 15;   // 0..15 -> out groups of 8
    float acc[4][8];
#pragma unroll
    for (int i = 0; i < 4; i++)
#pragma unroll
        for (int j = 0; j < 8; j++) acc[i][j] = 0.f;

    for (int kc = 0; kc < FIN * SSP; kc += 32) {
        // A tile: xa[n, k] = x[n, k/4] * attrs[n, k%4]
        for (int i = t; i < 32 * 64; i += 256) {
            int kk = i >> 6, n = i & 63;
            int k = kc + kk;
            int nn = n0 + n;
            float v = 0.f;
            if (nn < NN) v = x[nn * FIN + (k >> 2)] * attrs[nn * SSP + (k & 3)];
            sA[kk][n] = v;
        }
        // B tile: Wsc flat [1024, 256]
        for (int i = t; i < 32 * 128; i += 256) {
            int kk = i >> 7, o = i & 127;
            sB[kk][o] = Wsc[(kc + kk) * FOUT + o0 + o];
        }
        __syncthreads();
#pragma unroll 8
        for (int k = 0; k < 32; k++) {
            float a[4], b[8];
#pragma unroll
            for (int i = 0; i < 4; i++) a[i] = sA[k][tr * 4 + i];
#pragma unroll
            for (int j = 0; j < 8; j++) b[j] = sB[k][tc * 8 + j];
#pragma unroll
            for (int i = 0; i < 4; i++)
#pragma unroll
                for (int j = 0; j < 8; j++) acc[i][j] += a[i] * b[j];
        }
        __syncthreads();
    }
#pragma unroll
    for (int i = 0; i < 4; i++) {
        int nn = n0 + tr * 4 + i;
        if (nn >= NN) continue;
#pragma unroll
        for (int j = 0; j < 8; j++)
            out[nn * FOUT + o0 + tc * 8 + j] = acc[i][j];
    }
}

// ---------------------------------------------------------------------------
// fused edge kernel: radial MLP -> per-edge TP weights -> message -> scatter
// persistent blocks, 64 edges per tile, all MLP weights resident in smem
// ---------------------------------------------------------------------------
__global__ void __launch_bounds__(256, 1) k_edge(
    const float* __restrict__ eeG, const float* __restrict__ shG,
    const int* __restrict__ dstG, const int* __restrict__ srcG,
    const float* __restrict__ Wm1, const float* __restrict__ Wm2,
    const float* __restrict__ Wm3) {
    extern __shared__ float sm[];
    float* sWm1 = sm;                  // 512
    float* sWm2 = sWm1 + 512;          // 4096
    float* sWm3 = sWm2 + 4096;         // 18432
    float* sAct = sWm3 + 18432;        // 64*65 = 4160 (h1 then h2)
    float* sEE  = sAct + 4160;         // 512
    float* sSH  = sEE + 512;           // 576
    float* sHs  = sSH + 576;           // 2048 (gathered h[src])
    int*   sDst = (int*)(sHs + 2048);  // 64
    int*   sSrc = sDst + 64;           // 64

    int t = threadIdx.x;
    for (int i = t; i < 512;   i += 256) sWm1[i] = Wm1[i];
    for (int i = t; i < 4096;  i += 256) sWm2[i] = Wm2[i];
    for (int i = t; i < 18432; i += 256) sWm3[i] = Wm3[i];
    __syncthreads();

    const int e_loc = t & 63;
    const int j0 = (t >> 6) * 16;
    const int tx = t & 31, ty = t >> 5;

    for (int tile = blockIdx.x; tile < EE / 64; tile += gridDim.x) {
        int e0 = tile * 64;
        for (int i = t; i < 64 * BB; i += 256) sEE[i] = eeG[e0 * BB + i];
        for (int i = t; i < 64 * AA; i += 256) sSH[i] = shG[e0 * AA + i];
        if (t < 64) { sDst[t] = dstG[e0 + t]; sSrc[t] = srcG[e0 + t]; }
        __syncthreads();

        // gather h rows for sources (coalesced 128B per row)
        for (int i = t; i < 64 * CC; i += 256) {
            int e = i >> 5, c = i & 31;
            sHs[i] = g_h[sSrc[e] * CC + c];
        }

        // phase 1: h1 = silu(ee @ Wm1)  (each thread: 1 edge x 16 outputs)
        {
            float acc[16];
#pragma unroll
            for (int j = 0; j < 16; j++) acc[j] = 0.f;
#pragma unroll
            for (int b = 0; b < BB; b++) {
                float v = sEE[e_loc * BB + b];
#pragma unroll
                for (int j = 0; j < 16; j++) acc[j] += v * sWm1[b * HH + j0 + j];
            }
#pragma unroll
            for (int j = 0; j < 16; j++) sAct[e_loc * 65 + j0 + j] = silu_f(acc[j]);
        }
        __syncthreads();

        // phase 2: h2 = silu(h1 @ Wm2)
        {
            float acc[16];
#pragma unroll
            for (int j = 0; j < 16; j++) acc[j] = 0.f;
#pragma unroll 8
            for (int k = 0; k < HH; k++) {
                float v = sAct[e_loc * 65 + k];
#pragma unroll
                for (int j = 0; j < 16; j++) acc[j] += v * sWm2[k * HH + j0 + j];
            }
            __syncthreads();
#pragma unroll
            for (int j = 0; j < 16; j++) sAct[e_loc * 65 + j0 + j] = silu_f(acc[j]);
        }
        __syncthreads();

        // phase 3: w = h2 @ Wm3, fused TP + scatter
        // thread micro-tile: 8 edges (stride 8) x 9 outputs (stride 32)
        {
            float acc[8][9];
#pragma unroll
            for (int i = 0; i < 8; i++)
#pragma unroll
                for (int j = 0; j < 9; j++) acc[i][j] = 0.f;
#pragma unroll 4
            for (int k = 0; k < HH; k++) {
                float a[8], b[9];
#pragma unroll
                for (int i = 0; i < 8; i++) a[i] = sAct[(ty + 8 * i) * 65 + k];
#pragma unroll
                for (int j = 0; j < 9; j++) b[j] = sWm3[k * WN + tx + 32 * j];
#pragma unroll
                for (int i = 0; i < 8; i++)
#pragma unroll
                    for (int j = 0; j < 9; j++) acc[i][j] += a[i] * b[j];
            }
            // epilogue: msg = w * h[src,c] * sh[a]; coalesced scalar REDG
#pragma unroll
            for (int j = 0; j < 9; j++) {
                int o = tx + 32 * j;
                int c = o / 9;
                int a_ = o - c * 9;
#pragma unroll
                for (int i = 0; i < 8; i++) {
                    int e = ty + 8 * i;
                    float m = acc[i][j] * sHs[e * CC + c] * sSH[e * AA + a_];
                    atomicAdd(&g_agg[sDst[e] * WN + o], m);
                }
            }
        }
        __syncthreads();
    }
}

// ---------------------------------------------------------------------------
// out = silu(agg @ W2) + sc_out (already in out)
// tile 64 x 64, block 256, micro 4x4, K = 288
// ---------------------------------------------------------------------------
__global__ void __launch_bounds__(256) k_final(const float* __restrict__ W2,
                                               float* __restrict__ out) {
    __shared__ float sA[32][65];   // agg tile (k-major, padded)
    __shared__ float sB[32][64];
    int t = threadIdx.x;
    int n0 = blockIdx.x * 64;
    int o0 = blockIdx.y * 64;
    int tr = t >> 4, tc = t & 15;
    float acc[4][4];
#pragma unroll
    for (int i = 0; i < 4; i++)
#pragma unroll
        for (int j = 0; j < 4; j++) acc[i][j] = 0.f;

    for (int kc = 0; kc < WN; kc += 32) {
        for (int i = t; i < 64 * 32; i += 256) {
            int n = i >> 5, kk = i & 31;
            int nn = n0 + n;
            sA[kk][n] = (nn < NN) ? g_agg[nn * WN + kc + kk] : 0.f;
        }
        for (int i = t; i < 32 * 64; i += 256) {
            int kk = i >> 6, o = i & 63;
            sB[kk][o] = W2[(kc + kk) * FOUT + o0 + o];
        }
        __syncthreads();
#pragma unroll 8
        for (int k = 0; k < 32; k++) {
            float a[4], b[4];
#pragma unroll
            for (int i = 0; i < 4; i++) a[i] = sA[k][tr * 4 + i];
#pragma unroll
            for (int j = 0; j < 4; j++) b[j] = sB[k][tc * 4 + j];
#pragma unroll
            for (int i = 0; i < 4; i++)
#pragma unroll
                for (int j = 0; j < 4; j++) acc[i][j] += a[i] * b[j];
        }
        __syncthreads();
    }
#pragma unroll
    for (int i = 0; i < 4; i++) {
        int nn = n0 + tr * 4 + i;
        if (nn >= NN) continue;
#pragma unroll
        for (int j = 0; j < 4; j++) {
            int o = o0 + tc * 4 + j;
            out[nn * FOUT + o] = silu_f(acc[i][j]) + out[nn * FOUT + o];
        }
    }
}

// ---------------------------------------------------------------------------
extern "C" void kernel_launch(void* const* d_in, const int* in_sizes, int n_in,
                              void* d_out, int out_size) {
    const float* x     = (const float*)d_in[0];
    const float* attrs = (const float*)d_in[1];
    const float* ee    = (const float*)d_in[2];
    const float* sh    = (const float*)d_in[3];
    const int*   eidx  = (const int*)d_in[4];
    const float* W1    = (const float*)d_in[5];
    const float* Wm1   = (const float*)d_in[6];
    const float* Wm2   = (const float*)d_in[7];
    const float* Wm3   = (const float*)d_in[8];
    const float* W2    = (const float*)d_in[9];
    const float* Wsc   = (const float*)d_in[10];
    float* out = (float*)d_out;

    const int* dst = eidx;        // edge_index[0]
    const int* src = eidx + EE;   // edge_index[1]

    k_zero<<<1024, 256>>>();
    k_h<<<NN / 8, 256>>>(x, W1);

    dim3 gsc((NN + 63) / 64, 2);
    k_sc<<<gsc, 256>>>(x, attrs, Wsc, out);

    const int edge_smem = (512 + 4096 + 18432 + 4160 + 512 + 576 + 2048) * 4 + 128 * 4;
    cudaFuncSetAttribute(k_edge, cudaFuncAttributeMaxDynamicSharedMemorySize, edge_smem);
    k_edge<<<152, 256, edge_smem>>>(ee, sh, dst, src, Wm1, Wm2, Wm3);

    dim3 gf((NN + 63) / 64, 4);
    k_final<<<gf, 256>>>(W2, out);
}